// round 1
// baseline (speedup 1.0000x reference)
#include <cuda_runtime.h>
#include <math.h>

#define Bb    512
#define Tt    32
#define DEPTH 512
#define RNN   512
#define NCC   128
#define DIN   640          // DEPTH + NCC
#define G4    2048         // 4*RNN
#define BT    16384        // Bb*Tt
#define BRNN  (Bb*RNN)     // 262144

// ---------------- scratch (device globals: no allocation allowed) ----------
__device__ float g_X[BT * DIN];            // assembled inputs  [16384 x 640]
__device__ float g_Z[BT * G4];             // precomputed input gates [16384 x 2048]
__device__ float g_hall[(Tt + 1) * BRNN];  // h per step; slot 0 = zeros
__device__ float g_c0[BRNN];
__device__ float g_c1[BRNN];

// ---------------- init: zero h0 and c0 -------------------------------------
__global__ void init_zero_kernel() {
    int i = blockIdx.x * blockDim.x + threadIdx.x;
    if (i < BRNN) { g_hall[i] = 0.f; g_c0[i] = 0.f; }
}

// ---------------- assemble X = [f_pool[:,t,:], gt[:,t-1,:]] ----------------
__global__ void assemble_X_kernel(const float* __restrict__ f_pool,
                                  const float* __restrict__ gt) {
    int idx = blockIdx.x * blockDim.x + threadIdx.x;
    if (idx >= BT * DIN) return;
    int r = idx / DIN;          // r = b*32 + t
    int k = idx - r * DIN;
    float v;
    if (k < DEPTH) {
        v = f_pool[r * DEPTH + k];
    } else {
        int t = r & 31;
        v = (t == 0) ? 0.f : gt[(r - 1) * NCC + (k - DEPTH)];
    }
    g_X[idx] = v;
}

// ---------------- Z = X @ kernel + bias  (M=16384, N=2048, K=640) ----------
// 128x128 tile, BK=8, 256 threads, 8x8 microtile
__global__ __launch_bounds__(256) void gemm_Z_kernel(
    const float* __restrict__ W, const float* __restrict__ bias) {
    __shared__ float As[8][132];
    __shared__ float Bs[8][128];
    const int bx = blockIdx.x;       // 0..15   (N tiles)
    const int by = blockIdx.y;       // 0..127  (M tiles)
    const int tid = threadIdx.x;
    const int tx = tid & 15;
    const int ty = tid >> 4;
    const float* Abase = g_X + by * 128 * DIN;
    const float* Bbase = W + bx * 128;
    const int la_r = tid >> 1;
    const int la_k = (tid & 1) * 4;
    const int lb_k = tid >> 5;
    const int lb_j = (tid & 31) * 4;
    float acc[8][8];
    #pragma unroll
    for (int i = 0; i < 8; i++)
        #pragma unroll
        for (int j = 0; j < 8; j++) acc[i][j] = 0.f;

    for (int k0 = 0; k0 < DIN; k0 += 8) {
        float4 a = *(const float4*)(Abase + la_r * DIN + k0 + la_k);
        As[la_k + 0][la_r] = a.x; As[la_k + 1][la_r] = a.y;
        As[la_k + 2][la_r] = a.z; As[la_k + 3][la_r] = a.w;
        float4 b = *(const float4*)(Bbase + (k0 + lb_k) * G4 + lb_j);
        *(float4*)&Bs[lb_k][lb_j] = b;
        __syncthreads();
        #pragma unroll
        for (int kk = 0; kk < 8; kk++) {
            float av[8], bv[8];
            #pragma unroll
            for (int i = 0; i < 8; i++) av[i] = As[kk][ty * 8 + i];
            #pragma unroll
            for (int j = 0; j < 8; j++) bv[j] = Bs[kk][tx * 8 + j];
            #pragma unroll
            for (int i = 0; i < 8; i++)
                #pragma unroll
                for (int j = 0; j < 8; j++) acc[i][j] += av[i] * bv[j];
        }
        __syncthreads();
    }
    #pragma unroll
    for (int i = 0; i < 8; i++) {
        int row = by * 128 + ty * 8 + i;
        int col = bx * 128 + tx * 8;
        #pragma unroll
        for (int j = 0; j < 8; j += 4) {
            float4 v;
            v.x = acc[i][j + 0] + bias[col + j + 0];
            v.y = acc[i][j + 1] + bias[col + j + 1];
            v.z = acc[i][j + 2] + bias[col + j + 2];
            v.w = acc[i][j + 3] + bias[col + j + 3];
            *(float4*)&g_Z[row * G4 + col + j] = v;
        }
    }
}

// ---------------- one LSTM step: gates = Z_t + h@rec ; update c,h ----------
// grid: x = 8 (r tiles of 64), y = 16 (b tiles of 32). 256 threads.
// each thread: 8 b-rows (stride 4) x 1 r-col x 4 gates
__global__ __launch_bounds__(256) void lstm_step_kernel(
    int t, const float* __restrict__ rec) {
    __shared__ float As[16][33];
    __shared__ float Bs[16][256];
    const float* __restrict__ h_prev = g_hall + (size_t)t * BRNN;
    float* __restrict__ h_out = g_hall + (size_t)(t + 1) * BRNN;
    const float* __restrict__ c_prev = (t & 1) ? g_c1 : g_c0;
    float* __restrict__ c_out = (t & 1) ? g_c0 : g_c1;

    const int r0 = blockIdx.x * 64;
    const int b0 = blockIdx.y * 32;
    const int tid = threadIdx.x;
    const int tx = tid & 63;    // r within tile
    const int ty = tid >> 6;    // 0..3
    const int la_b = tid >> 3;         // 0..31
    const int la_k = (tid & 7) * 2;    // 0..14
    const int lb_k = tid >> 4;         // 0..15
    const int lb_j = (tid & 15) * 4;   // 0..60

    float acc[8][4];
    #pragma unroll
    for (int i = 0; i < 8; i++)
        #pragma unroll
        for (int g = 0; g < 4; g++) acc[i][g] = 0.f;

    for (int k0 = 0; k0 < RNN; k0 += 16) {
        float2 a = *(const float2*)(h_prev + (b0 + la_b) * RNN + k0 + la_k);
        As[la_k + 0][la_b] = a.x;
        As[la_k + 1][la_b] = a.y;
        #pragma unroll
        for (int g = 0; g < 4; g++) {
            float4 bb = *(const float4*)(rec + (k0 + lb_k) * G4 + g * RNN + r0 + lb_j);
            *(float4*)&Bs[lb_k][g * 64 + lb_j] = bb;
        }
        __syncthreads();
        #pragma unroll
        for (int kk = 0; kk < 16; kk++) {
            float bv[4];
            #pragma unroll
            for (int g = 0; g < 4; g++) bv[g] = Bs[kk][g * 64 + tx];
            #pragma unroll
            for (int i = 0; i < 8; i++) {
                float av = As[kk][ty + i * 4];
                #pragma unroll
                for (int g = 0; g < 4; g++) acc[i][g] += av * bv[g];
            }
        }
        __syncthreads();
    }

    const int r = r0 + tx;
    #pragma unroll
    for (int i = 0; i < 8; i++) {
        int b = b0 + ty + i * 4;
        int zb = (b * Tt + t) * G4 + r;
        float iG = acc[i][0] + g_Z[zb];
        float fG = acc[i][1] + g_Z[zb + RNN];
        float gG = acc[i][2] + g_Z[zb + 2 * RNN];
        float oG = acc[i][3] + g_Z[zb + 3 * RNN];
        float si = 1.f / (1.f + expf(-iG));
        float sf = 1.f / (1.f + expf(-fG));
        float so = 1.f / (1.f + expf(-oG));
        float c2 = sf * c_prev[b * RNN + r] + si * tanhf(gG);
        float h2 = so * tanhf(c2);
        c_out[b * RNN + r] = c2;
        h_out[b * RNN + r] = h2;
    }
}

// ---------------- batched logits + argmax + one-hot -------------------------
// Hall rows: R = t*512 + b (slots 1..32 contiguous). M=16384, N=128, K=512.
// 128x128 tile (full N), BK=8, 256 threads, 8x8 microtile, fused argmax.
__global__ __launch_bounds__(256) void logits_argmax_kernel(
    const float* __restrict__ sw, const float* __restrict__ sb,
    float* __restrict__ out) {
    __shared__ float As[8][132];
    __shared__ float Bs[8][128];
    const int by = blockIdx.x;   // 0..127
    const int tid = threadIdx.x;
    const int tx = tid & 15;
    const int ty = tid >> 4;
    const float* Abase = g_hall + BRNN + (size_t)by * 128 * RNN;
    const int la_r = tid >> 1;
    const int la_k = (tid & 1) * 4;
    const int lb_k = tid >> 5;
    const int lb_j = (tid & 31) * 4;

    float acc[8][8];
    #pragma unroll
    for (int i = 0; i < 8; i++)
        #pragma unroll
        for (int j = 0; j < 8; j++) acc[i][j] = 0.f;

    for (int k0 = 0; k0 < RNN; k0 += 8) {
        float4 a = *(const float4*)(Abase + la_r * RNN + k0 + la_k);
        As[la_k + 0][la_r] = a.x; As[la_k + 1][la_r] = a.y;
        As[la_k + 2][la_r] = a.z; As[la_k + 3][la_r] = a.w;
        float4 b = *(const float4*)(sw + (k0 + lb_k) * NCC + lb_j);
        *(float4*)&Bs[lb_k][lb_j] = b;
        __syncthreads();
        #pragma unroll
        for (int kk = 0; kk < 8; kk++) {
            float av[8], bv[8];
            #pragma unroll
            for (int i = 0; i < 8; i++) av[i] = As[kk][ty * 8 + i];
            #pragma unroll
            for (int j = 0; j < 8; j++) bv[j] = Bs[kk][tx * 8 + j];
            #pragma unroll
            for (int i = 0; i < 8; i++)
                #pragma unroll
                for (int j = 0; j < 8; j++) acc[i][j] += av[i] * bv[j];
        }
        __syncthreads();
    }

    // per-row argmax over the 128 columns (held by 16 threads of same ty)
    #pragma unroll
    for (int i = 0; i < 8; i++) {
        float best = -1e30f;
        int bidx = 0;
        #pragma unroll
        for (int j = 0; j < 8; j++) {
            float v = acc[i][j] + sb[tx * 8 + j];
            acc[i][j] = v;
            if (v > best) { best = v; bidx = tx * 8 + j; }  // ascending scan keeps first max
        }
        #pragma unroll
        for (int off = 8; off >= 1; off >>= 1) {
            float ob = __shfl_xor_sync(0xffffffffu, best, off);
            int oi = __shfl_xor_sync(0xffffffffu, bidx, off);
            if (ob > best || (ob == best && oi < bidx)) { best = ob; bidx = oi; }
        }
        int R = by * 128 + ty * 8 + i;   // R = t*512 + b
        int t = R >> 9;
        int b = R & 511;
        float* orow = out + (size_t)b * (Tt * NCC) + t * NCC;
        #pragma unroll
        for (int j = 0; j < 8; j++) {
            int col = tx * 8 + j;
            orow[col] = (col == bidx) ? 1.f : 0.f;
        }
    }
}

// ---------------- copy final h, c to output ---------------------------------
__global__ void copy_final_kernel(float* __restrict__ out) {
    int i = blockIdx.x * blockDim.x + threadIdx.x;
    if (i < BRNN) {
        out[BT * NCC + i] = g_hall[(size_t)Tt * BRNN + i];       // final h
        out[BT * NCC + BRNN + i] = g_c0[i];                      // final c (t=31 odd -> wrote c0)
    }
}

// ---------------- launch -----------------------------------------------------
extern "C" void kernel_launch(void* const* d_in, const int* in_sizes, int n_in,
                              void* d_out, int out_size) {
    const float* f_pool = (const float*)d_in[0];
    const float* gt     = (const float*)d_in[1];
    const float* W      = (const float*)d_in[2];
    const float* rec    = (const float*)d_in[3];
    const float* bias   = (const float*)d_in[4];
    const float* sw     = (const float*)d_in[5];
    const float* sb     = (const float*)d_in[6];
    float* out = (float*)d_out;

    init_zero_kernel<<<(BRNN + 255) / 256, 256>>>();
    assemble_X_kernel<<<(BT * DIN + 255) / 256, 256>>>(f_pool, gt);

    dim3 gz(16, 128);
    gemm_Z_kernel<<<gz, 256>>>(W, bias);

    for (int t = 0; t < Tt; t++) {
        dim3 gs(8, 16);
        lstm_step_kernel<<<gs, 256>>>(t, rec);
    }

    logits_argmax_kernel<<<128, 256>>>(sw, sb, out);
    copy_final_kernel<<<(BRNN + 255) / 256, 256>>>(out);
}

// round 2
// speedup vs baseline: 1.2771x; 1.2771x over previous
#include <cuda_runtime.h>
#include <math.h>

#define Bb    512
#define Tt    32
#define DEPTH 512
#define RNN   512
#define NCC   128
#define DIN   640          // DEPTH + NCC
#define G4    2048         // 4*RNN
#define BT    16384        // Bb*Tt
#define BRNN  (Bb*RNN)     // 262144
#define KS    4            // split-K slices for recurrent GEMM

// ---------------- scratch (device globals: no allocation allowed) ----------
__device__ float g_X[BT * DIN];            // assembled inputs  [16384 x 640]
__device__ float g_Z[BT * G4];             // precomputed input gates [16384 x 2048]
__device__ float g_hall[(Tt + 1) * BRNN];  // h per step; slot 0 = zeros
__device__ float g_c0[BRNN];
__device__ float g_c1[BRNN];
__device__ float g_part[KS * Bb * G4];     // split-K partials [4][512][2048] = 16MB

// ---------------- init: zero h0 and c0 -------------------------------------
__global__ void init_zero_kernel() {
    int i = blockIdx.x * blockDim.x + threadIdx.x;
    if (i < BRNN) { g_hall[i] = 0.f; g_c0[i] = 0.f; }
}

// ---------------- assemble X = [f_pool[:,t,:], gt[:,t-1,:]] ----------------
__global__ void assemble_X_kernel(const float* __restrict__ f_pool,
                                  const float* __restrict__ gt) {
    int idx = blockIdx.x * blockDim.x + threadIdx.x;
    if (idx >= BT * DIN) return;
    int r = idx / DIN;          // r = b*32 + t
    int k = idx - r * DIN;
    float v;
    if (k < DEPTH) {
        v = f_pool[r * DEPTH + k];
    } else {
        int t = r & 31;
        v = (t == 0) ? 0.f : gt[(r - 1) * NCC + (k - DEPTH)];
    }
    g_X[idx] = v;
}

// ---------------- Z = X @ kernel + bias  (M=16384, N=2048, K=640) ----------
// 128x128 tile, BK=8, 256 threads, 8x8 microtile
__global__ __launch_bounds__(256) void gemm_Z_kernel(
    const float* __restrict__ W, const float* __restrict__ bias) {
    __shared__ float As[8][132];
    __shared__ float Bs[8][128];
    const int bx = blockIdx.x;       // 0..15   (N tiles)
    const int by = blockIdx.y;       // 0..127  (M tiles)
    const int tid = threadIdx.x;
    const int tx = tid & 15;
    const int ty = tid >> 4;
    const float* Abase = g_X + by * 128 * DIN;
    const float* Bbase = W + bx * 128;
    const int la_r = tid >> 1;
    const int la_k = (tid & 1) * 4;
    const int lb_k = tid >> 5;
    const int lb_j = (tid & 31) * 4;
    float acc[8][8];
    #pragma unroll
    for (int i = 0; i < 8; i++)
        #pragma unroll
        for (int j = 0; j < 8; j++) acc[i][j] = 0.f;

    for (int k0 = 0; k0 < DIN; k0 += 8) {
        float4 a = *(const float4*)(Abase + la_r * DIN + k0 + la_k);
        As[la_k + 0][la_r] = a.x; As[la_k + 1][la_r] = a.y;
        As[la_k + 2][la_r] = a.z; As[la_k + 3][la_r] = a.w;
        float4 b = *(const float4*)(Bbase + (k0 + lb_k) * G4 + lb_j);
        *(float4*)&Bs[lb_k][lb_j] = b;
        __syncthreads();
        #pragma unroll
        for (int kk = 0; kk < 8; kk++) {
            float av[8], bv[8];
            #pragma unroll
            for (int i = 0; i < 8; i++) av[i] = As[kk][ty * 8 + i];
            #pragma unroll
            for (int j = 0; j < 8; j++) bv[j] = Bs[kk][tx * 8 + j];
            #pragma unroll
            for (int i = 0; i < 8; i++)
                #pragma unroll
                for (int j = 0; j < 8; j++) acc[i][j] += av[i] * bv[j];
        }
        __syncthreads();
    }
    #pragma unroll
    for (int i = 0; i < 8; i++) {
        int row = by * 128 + ty * 8 + i;
        int col = bx * 128 + tx * 8;
        #pragma unroll
        for (int j = 0; j < 8; j += 4) {
            float4 v;
            v.x = acc[i][j + 0] + bias[col + j + 0];
            v.y = acc[i][j + 1] + bias[col + j + 1];
            v.z = acc[i][j + 2] + bias[col + j + 2];
            v.w = acc[i][j + 3] + bias[col + j + 3];
            *(float4*)&g_Z[row * G4 + col + j] = v;
        }
    }
}

// ---------------- recurrent GEMM: partials = h_prev @ rec (split-K=4) -------
// M=512 (batch), N=2048 (gates), K=512 split into 4 slices of 128.
// grid (16 n-tiles, 4 m-tiles, 4 k-slices) = 256 blocks, 256 threads each.
__global__ __launch_bounds__(256) void lstm_gemm_kernel(
    int t, const float* __restrict__ rec) {
    __shared__ float As[8][132];
    __shared__ float Bs[8][128];
    const int n0 = blockIdx.x * 128;
    const int m0 = blockIdx.y * 128;
    const int kb = blockIdx.z * 128;
    const float* __restrict__ A = g_hall + (size_t)t * BRNN;  // [512 x 512]
    const int tid = threadIdx.x;
    const int tx = tid & 15;
    const int ty = tid >> 4;
    const int la_r = tid >> 1;
    const int la_k = (tid & 1) * 4;
    const int lb_k = tid >> 5;
    const int lb_j = (tid & 31) * 4;
    float acc[8][8];
    #pragma unroll
    for (int i = 0; i < 8; i++)
        #pragma unroll
        for (int j = 0; j < 8; j++) acc[i][j] = 0.f;

    #pragma unroll 1
    for (int k0 = 0; k0 < 128; k0 += 8) {
        float4 a = *(const float4*)(A + (m0 + la_r) * RNN + kb + k0 + la_k);
        As[la_k + 0][la_r] = a.x; As[la_k + 1][la_r] = a.y;
        As[la_k + 2][la_r] = a.z; As[la_k + 3][la_r] = a.w;
        float4 b = *(const float4*)(rec + (kb + k0 + lb_k) * G4 + n0 + lb_j);
        *(float4*)&Bs[lb_k][lb_j] = b;
        __syncthreads();
        #pragma unroll
        for (int kk = 0; kk < 8; kk++) {
            float av[8], bv[8];
            #pragma unroll
            for (int i = 0; i < 8; i++) av[i] = As[kk][ty * 8 + i];
            #pragma unroll
            for (int j = 0; j < 8; j++) bv[j] = Bs[kk][tx * 8 + j];
            #pragma unroll
            for (int i = 0; i < 8; i++)
                #pragma unroll
                for (int j = 0; j < 8; j++) acc[i][j] += av[i] * bv[j];
        }
        __syncthreads();
    }

    float* __restrict__ P = g_part + (size_t)blockIdx.z * (Bb * G4);
    #pragma unroll
    for (int i = 0; i < 8; i++) {
        int row = m0 + ty * 8 + i;
        int col = n0 + tx * 8;
        #pragma unroll
        for (int j = 0; j < 8; j += 4) {
            float4 v;
            v.x = acc[i][j + 0]; v.y = acc[i][j + 1];
            v.z = acc[i][j + 2]; v.w = acc[i][j + 3];
            *(float4*)&P[(size_t)row * G4 + col + j] = v;
        }
    }
}

// ---------------- gating: combine partials + Z + c -> h,c -------------------
// one thread per 4 consecutive r of one batch row; 65536 threads.
__device__ __forceinline__ float sigm(float x) { return 1.f / (1.f + expf(-x)); }

__global__ __launch_bounds__(256) void gate_kernel(int t, int use_part) {
    int idx = blockIdx.x * blockDim.x + threadIdx.x;
    if (idx >= Bb * (RNN / 4)) return;
    int r4 = (idx & 127) * 4;
    int b  = idx >> 7;
    const float* __restrict__ c_prev = (t & 1) ? g_c1 : g_c0;
    float* __restrict__ c_out = (t & 1) ? g_c0 : g_c1;
    float* __restrict__ h_out = g_hall + (size_t)(t + 1) * BRNN;

    float4 gz[4];
    #pragma unroll
    for (int g = 0; g < 4; g++) {
        size_t zo = ((size_t)b * Tt + t) * G4 + g * RNN + r4;
        float4 s = *(const float4*)(g_Z + zo);
        if (use_part) {
            size_t po = (size_t)b * G4 + g * RNN + r4;
            #pragma unroll
            for (int ks = 0; ks < KS; ks++) {
                float4 p = *(const float4*)(g_part + (size_t)ks * (Bb * G4) + po);
                s.x += p.x; s.y += p.y; s.z += p.z; s.w += p.w;
            }
        }
        gz[g] = s;
    }
    float4 cp = *(const float4*)(c_prev + (size_t)b * RNN + r4);

    float4 cv, hv;
    {
        float c2, h2;
        c2 = sigm(gz[1].x) * cp.x + sigm(gz[0].x) * tanhf(gz[2].x);
        h2 = sigm(gz[3].x) * tanhf(c2); cv.x = c2; hv.x = h2;
        c2 = sigm(gz[1].y) * cp.y + sigm(gz[0].y) * tanhf(gz[2].y);
        h2 = sigm(gz[3].y) * tanhf(c2); cv.y = c2; hv.y = h2;
        c2 = sigm(gz[1].z) * cp.z + sigm(gz[0].z) * tanhf(gz[2].z);
        h2 = sigm(gz[3].z) * tanhf(c2); cv.z = c2; hv.z = h2;
        c2 = sigm(gz[1].w) * cp.w + sigm(gz[0].w) * tanhf(gz[2].w);
        h2 = sigm(gz[3].w) * tanhf(c2); cv.w = c2; hv.w = h2;
    }
    *(float4*)(c_out + (size_t)b * RNN + r4) = cv;
    *(float4*)(h_out + (size_t)b * RNN + r4) = hv;
}

// ---------------- batched logits + argmax + one-hot -------------------------
__global__ __launch_bounds__(256) void logits_argmax_kernel(
    const float* __restrict__ sw, const float* __restrict__ sb,
    float* __restrict__ out) {
    __shared__ float As[8][132];
    __shared__ float Bs[8][128];
    const int by = blockIdx.x;   // 0..127
    const int tid = threadIdx.x;
    const int tx = tid & 15;
    const int ty = tid >> 4;
    const float* Abase = g_hall + BRNN + (size_t)by * 128 * RNN;
    const int la_r = tid >> 1;
    const int la_k = (tid & 1) * 4;
    const int lb_k = tid >> 5;
    const int lb_j = (tid & 31) * 4;

    float acc[8][8];
    #pragma unroll
    for (int i = 0; i < 8; i++)
        #pragma unroll
        for (int j = 0; j < 8; j++) acc[i][j] = 0.f;

    for (int k0 = 0; k0 < RNN; k0 += 8) {
        float4 a = *(const float4*)(Abase + la_r * RNN + k0 + la_k);
        As[la_k + 0][la_r] = a.x; As[la_k + 1][la_r] = a.y;
        As[la_k + 2][la_r] = a.z; As[la_k + 3][la_r] = a.w;
        float4 b = *(const float4*)(sw + (k0 + lb_k) * NCC + lb_j);
        *(float4*)&Bs[lb_k][lb_j] = b;
        __syncthreads();
        #pragma unroll
        for (int kk = 0; kk < 8; kk++) {
            float av[8], bv[8];
            #pragma unroll
            for (int i = 0; i < 8; i++) av[i] = As[kk][ty * 8 + i];
            #pragma unroll
            for (int j = 0; j < 8; j++) bv[j] = Bs[kk][tx * 8 + j];
            #pragma unroll
            for (int i = 0; i < 8; i++)
                #pragma unroll
                for (int j = 0; j < 8; j++) acc[i][j] += av[i] * bv[j];
        }
        __syncthreads();
    }

    #pragma unroll
    for (int i = 0; i < 8; i++) {
        float best = -1e30f;
        int bidx = 0;
        #pragma unroll
        for (int j = 0; j < 8; j++) {
            float v = acc[i][j] + sb[tx * 8 + j];
            acc[i][j] = v;
            if (v > best) { best = v; bidx = tx * 8 + j; }
        }
        #pragma unroll
        for (int off = 8; off >= 1; off >>= 1) {
            float ob = __shfl_xor_sync(0xffffffffu, best, off);
            int oi = __shfl_xor_sync(0xffffffffu, bidx, off);
            if (ob > best || (ob == best && oi < bidx)) { best = ob; bidx = oi; }
        }
        int R = by * 128 + ty * 8 + i;   // R = t*512 + b
        int t = R >> 9;
        int b = R & 511;
        float* orow = out + (size_t)b * (Tt * NCC) + t * NCC;
        #pragma unroll
        for (int j = 0; j < 8; j++) {
            int col = tx * 8 + j;
            orow[col] = (col == bidx) ? 1.f : 0.f;
        }
    }
}

// ---------------- copy final h, c to output ---------------------------------
__global__ void copy_final_kernel(float* __restrict__ out) {
    int i = blockIdx.x * blockDim.x + threadIdx.x;
    if (i < BRNN) {
        out[BT * NCC + i] = g_hall[(size_t)Tt * BRNN + i];       // final h
        out[BT * NCC + BRNN + i] = g_c0[i];                      // final c (t=31 odd -> c0)
    }
}

// ---------------- launch -----------------------------------------------------
extern "C" void kernel_launch(void* const* d_in, const int* in_sizes, int n_in,
                              void* d_out, int out_size) {
    const float* f_pool = (const float*)d_in[0];
    const float* gt     = (const float*)d_in[1];
    const float* W      = (const float*)d_in[2];
    const float* rec    = (const float*)d_in[3];
    const float* bias   = (const float*)d_in[4];
    const float* sw     = (const float*)d_in[5];
    const float* sb     = (const float*)d_in[6];
    float* out = (float*)d_out;

    init_zero_kernel<<<(BRNN + 255) / 256, 256>>>();
    assemble_X_kernel<<<(BT * DIN + 255) / 256, 256>>>(f_pool, gt);

    dim3 gz(16, 128);
    gemm_Z_kernel<<<gz, 256>>>(W, bias);

    const int gate_threads = Bb * (RNN / 4);
    for (int t = 0; t < Tt; t++) {
        if (t > 0) {
            dim3 gg(16, 4, KS);
            lstm_gemm_kernel<<<gg, 256>>>(t, rec);
        }
        gate_kernel<<<(gate_threads + 255) / 256, 256>>>(t, t > 0 ? 1 : 0);
    }

    logits_argmax_kernel<<<128, 256>>>(sw, sb, out);
    copy_final_kernel<<<(BRNN + 255) / 256, 256>>>(out);
}

// round 3
// speedup vs baseline: 1.3922x; 1.0901x over previous
#include <cuda_runtime.h>
#include <math.h>

#define Bb    512
#define Tt    32
#define DEPTH 512
#define RNN   512
#define NCC   128
#define DIN   640          // DEPTH + NCC
#define G4    2048         // 4*RNN
#define BT    16384        // Bb*Tt
#define BRNN  (Bb*RNN)     // 262144
#define KS    4            // split-K slices for recurrent GEMM

// ---------------- scratch (device globals: no allocation allowed) ----------
__device__ float g_X[BT * DIN];            // assembled inputs  [16384 x 640]
__device__ float g_Z[BT * G4];             // precomputed input gates [16384 x 2048]
__device__ float g_hall[(Tt + 1) * BRNN];  // h per step; slot 0 = zeros
__device__ float g_c0[BRNN];
__device__ float g_c1[BRNN];
__device__ float g_part[KS * Bb * G4];     // split-K partials [4][512][2048]

// ---------------- init: zero h0 and c0 -------------------------------------
__global__ void init_zero_kernel() {
    int i = blockIdx.x * blockDim.x + threadIdx.x;
    if (i < BRNN) { g_hall[i] = 0.f; g_c0[i] = 0.f; }
}

// ---------------- assemble X = [f_pool[:,t,:], gt[:,t-1,:]] ----------------
__global__ void assemble_X_kernel(const float* __restrict__ f_pool,
                                  const float* __restrict__ gt) {
    int idx = blockIdx.x * blockDim.x + threadIdx.x;
    if (idx >= BT * DIN) return;
    int r = idx / DIN;          // r = b*32 + t
    int k = idx - r * DIN;
    float v;
    if (k < DEPTH) {
        v = f_pool[r * DEPTH + k];
    } else {
        int t = r & 31;
        v = (t == 0) ? 0.f : gt[(r - 1) * NCC + (k - DEPTH)];
    }
    g_X[idx] = v;
}

// ============================================================================
// Pipelined 128x128 GEMM bodies: double-buffered smem + register prefetch,
// ONE __syncthreads per k-iteration. 256 threads, 8x8 microtile.
// ============================================================================

// ---------------- Z = X @ kernel + bias  (M=16384, N=2048, K=640) ----------
__global__ __launch_bounds__(256) void gemm_Z_kernel(
    const float* __restrict__ W, const float* __restrict__ bias) {
    __shared__ float As[2][8][132];
    __shared__ float Bs[2][8][128];
    const int bx = blockIdx.x;       // 0..15   (N tiles)
    const int by = blockIdx.y;       // 0..127  (M tiles)
    const int tid = threadIdx.x;
    const int tx = tid & 15;
    const int ty = tid >> 4;
    const int la_r = tid >> 1;
    const int la_k = (tid & 1) * 4;
    const int lb_k = tid >> 5;
    const int lb_j = (tid & 31) * 4;
    const float* Aptr = g_X + (size_t)(by * 128 + la_r) * DIN + la_k;
    const float* Bptr = W + (size_t)lb_k * G4 + bx * 128 + lb_j;

    float acc[8][8];
    #pragma unroll
    for (int i = 0; i < 8; i++)
        #pragma unroll
        for (int j = 0; j < 8; j++) acc[i][j] = 0.f;

    float4 aN = *(const float4*)(Aptr);
    float4 bN = *(const float4*)(Bptr);
    int buf = 0;
    for (int k0 = 0; k0 < DIN; k0 += 8) {
        As[buf][la_k + 0][la_r] = aN.x; As[buf][la_k + 1][la_r] = aN.y;
        As[buf][la_k + 2][la_r] = aN.z; As[buf][la_k + 3][la_r] = aN.w;
        *(float4*)&Bs[buf][lb_k][lb_j] = bN;
        if (k0 + 8 < DIN) {
            aN = *(const float4*)(Aptr + k0 + 8);
            bN = *(const float4*)(Bptr + (size_t)(k0 + 8) * G4);
        }
        __syncthreads();
        #pragma unroll
        for (int kk = 0; kk < 8; kk++) {
            float av[8], bv[8];
            #pragma unroll
            for (int i = 0; i < 8; i++) av[i] = As[buf][kk][ty * 8 + i];
            #pragma unroll
            for (int j = 0; j < 8; j++) bv[j] = Bs[buf][kk][tx * 8 + j];
            #pragma unroll
            for (int i = 0; i < 8; i++)
                #pragma unroll
                for (int j = 0; j < 8; j++) acc[i][j] += av[i] * bv[j];
        }
        buf ^= 1;
    }
    #pragma unroll
    for (int i = 0; i < 8; i++) {
        int row = by * 128 + ty * 8 + i;
        int col = bx * 128 + tx * 8;
        #pragma unroll
        for (int j = 0; j < 8; j += 4) {
            float4 v;
            v.x = acc[i][j + 0] + bias[col + j + 0];
            v.y = acc[i][j + 1] + bias[col + j + 1];
            v.z = acc[i][j + 2] + bias[col + j + 2];
            v.w = acc[i][j + 3] + bias[col + j + 3];
            *(float4*)&g_Z[(size_t)row * G4 + col + j] = v;
        }
    }
}

// ---------------- recurrent GEMM: partials = h_prev @ rec (split-K=4) -------
// M=512, N=2048, K=512 split into 4 slices of 128. grid (16,4,4), 256 thr.
__global__ __launch_bounds__(256) void lstm_gemm_kernel(
    int t, const float* __restrict__ rec) {
    __shared__ float As[2][8][132];
    __shared__ float Bs[2][8][128];
    const int n0 = blockIdx.x * 128;
    const int m0 = blockIdx.y * 128;
    const int kb = blockIdx.z * 128;
    const float* __restrict__ A = g_hall + (size_t)t * BRNN;  // [512 x 512]
    const int tid = threadIdx.x;
    const int tx = tid & 15;
    const int ty = tid >> 4;
    const int la_r = tid >> 1;
    const int la_k = (tid & 1) * 4;
    const int lb_k = tid >> 5;
    const int lb_j = (tid & 31) * 4;
    const float* Aptr = A + (size_t)(m0 + la_r) * RNN + kb + la_k;
    const float* Bptr = rec + (size_t)(kb + lb_k) * G4 + n0 + lb_j;

    float acc[8][8];
    #pragma unroll
    for (int i = 0; i < 8; i++)
        #pragma unroll
        for (int j = 0; j < 8; j++) acc[i][j] = 0.f;

    float4 aN = *(const float4*)(Aptr);
    float4 bN = *(const float4*)(Bptr);
    int buf = 0;
    #pragma unroll 4
    for (int k0 = 0; k0 < 128; k0 += 8) {
        As[buf][la_k + 0][la_r] = aN.x; As[buf][la_k + 1][la_r] = aN.y;
        As[buf][la_k + 2][la_r] = aN.z; As[buf][la_k + 3][la_r] = aN.w;
        *(float4*)&Bs[buf][lb_k][lb_j] = bN;
        if (k0 + 8 < 128) {
            aN = *(const float4*)(Aptr + k0 + 8);
            bN = *(const float4*)(Bptr + (size_t)(k0 + 8) * G4);
        }
        __syncthreads();
        #pragma unroll
        for (int kk = 0; kk < 8; kk++) {
            float av[8], bv[8];
            #pragma unroll
            for (int i = 0; i < 8; i++) av[i] = As[buf][kk][ty * 8 + i];
            #pragma unroll
            for (int j = 0; j < 8; j++) bv[j] = Bs[buf][kk][tx * 8 + j];
            #pragma unroll
            for (int i = 0; i < 8; i++)
                #pragma unroll
                for (int j = 0; j < 8; j++) acc[i][j] += av[i] * bv[j];
        }
        buf ^= 1;
    }

    float* __restrict__ P = g_part + (size_t)blockIdx.z * (Bb * G4);
    #pragma unroll
    for (int i = 0; i < 8; i++) {
        int row = m0 + ty * 8 + i;
        int col = n0 + tx * 8;
        #pragma unroll
        for (int j = 0; j < 8; j += 4) {
            float4 v;
            v.x = acc[i][j + 0]; v.y = acc[i][j + 1];
            v.z = acc[i][j + 2]; v.w = acc[i][j + 3];
            *(float4*)&P[(size_t)row * G4 + col + j] = v;
        }
    }
}

// ---------------- gating: combine partials + Z + c -> h,c -------------------
__device__ __forceinline__ float sigm(float x) { return 1.f / (1.f + expf(-x)); }

__global__ __launch_bounds__(256) void gate_kernel(int t, int use_part) {
    int idx = blockIdx.x * blockDim.x + threadIdx.x;
    if (idx >= Bb * (RNN / 4)) return;
    int r4 = (idx & 127) * 4;
    int b  = idx >> 7;
    const float* __restrict__ c_prev = (t & 1) ? g_c1 : g_c0;
    float* __restrict__ c_out = (t & 1) ? g_c0 : g_c1;
    float* __restrict__ h_out = g_hall + (size_t)(t + 1) * BRNN;

    float4 gz[4];
    #pragma unroll
    for (int g = 0; g < 4; g++) {
        size_t zo = ((size_t)b * Tt + t) * G4 + g * RNN + r4;
        float4 s = *(const float4*)(g_Z + zo);
        if (use_part) {
            size_t po = (size_t)b * G4 + g * RNN + r4;
            #pragma unroll
            for (int ks = 0; ks < KS; ks++) {
                float4 p = *(const float4*)(g_part + (size_t)ks * (Bb * G4) + po);
                s.x += p.x; s.y += p.y; s.z += p.z; s.w += p.w;
            }
        }
        gz[g] = s;
    }
    float4 cp = *(const float4*)(c_prev + (size_t)b * RNN + r4);

    float4 cv, hv;
    {
        float c2;
        c2 = sigm(gz[1].x) * cp.x + sigm(gz[0].x) * tanhf(gz[2].x);
        cv.x = c2; hv.x = sigm(gz[3].x) * tanhf(c2);
        c2 = sigm(gz[1].y) * cp.y + sigm(gz[0].y) * tanhf(gz[2].y);
        cv.y = c2; hv.y = sigm(gz[3].y) * tanhf(c2);
        c2 = sigm(gz[1].z) * cp.z + sigm(gz[0].z) * tanhf(gz[2].z);
        cv.z = c2; hv.z = sigm(gz[3].z) * tanhf(c2);
        c2 = sigm(gz[1].w) * cp.w + sigm(gz[0].w) * tanhf(gz[2].w);
        cv.w = c2; hv.w = sigm(gz[3].w) * tanhf(c2);
    }
    *(float4*)(c_out + (size_t)b * RNN + r4) = cv;
    *(float4*)(h_out + (size_t)b * RNN + r4) = hv;
}

// ---------------- batched logits + argmax + one-hot -------------------------
// M=16384, N=128 (full), K=512. Pipelined like the others.
__global__ __launch_bounds__(256) void logits_argmax_kernel(
    const float* __restrict__ sw, const float* __restrict__ sb,
    float* __restrict__ out) {
    __shared__ float As[2][8][132];
    __shared__ float Bs[2][8][128];
    const int by = blockIdx.x;   // 0..127
    const int tid = threadIdx.x;
    const int tx = tid & 15;
    const int ty = tid >> 4;
    const int la_r = tid >> 1;
    const int la_k = (tid & 1) * 4;
    const int lb_k = tid >> 5;
    const int lb_j = (tid & 31) * 4;
    const float* Aptr = g_hall + BRNN + (size_t)(by * 128 + la_r) * RNN + la_k;
    const float* Bptr = sw + (size_t)lb_k * NCC + lb_j;

    float acc[8][8];
    #pragma unroll
    for (int i = 0; i < 8; i++)
        #pragma unroll
        for (int j = 0; j < 8; j++) acc[i][j] = 0.f;

    float4 aN = *(const float4*)(Aptr);
    float4 bN = *(const float4*)(Bptr);
    int buf = 0;
    for (int k0 = 0; k0 < RNN; k0 += 8) {
        As[buf][la_k + 0][la_r] = aN.x; As[buf][la_k + 1][la_r] = aN.y;
        As[buf][la_k + 2][la_r] = aN.z; As[buf][la_k + 3][la_r] = aN.w;
        *(float4*)&Bs[buf][lb_k][lb_j] = bN;
        if (k0 + 8 < RNN) {
            aN = *(const float4*)(Aptr + k0 + 8);
            bN = *(const float4*)(Bptr + (size_t)(k0 + 8) * NCC);
        }
        __syncthreads();
        #pragma unroll
        for (int kk = 0; kk < 8; kk++) {
            float av[8], bv[8];
            #pragma unroll
            for (int i = 0; i < 8; i++) av[i] = As[buf][kk][ty * 8 + i];
            #pragma unroll
            for (int j = 0; j < 8; j++) bv[j] = Bs[buf][kk][tx * 8 + j];
            #pragma unroll
            for (int i = 0; i < 8; i++)
                #pragma unroll
                for (int j = 0; j < 8; j++) acc[i][j] += av[i] * bv[j];
        }
        buf ^= 1;
    }

    #pragma unroll
    for (int i = 0; i < 8; i++) {
        float best = -1e30f;
        int bidx = 0;
        #pragma unroll
        for (int j = 0; j < 8; j++) {
            float v = acc[i][j] + sb[tx * 8 + j];
            if (v > best) { best = v; bidx = tx * 8 + j; }
        }
        #pragma unroll
        for (int off = 8; off >= 1; off >>= 1) {
            float ob = __shfl_xor_sync(0xffffffffu, best, off);
            int oi = __shfl_xor_sync(0xffffffffu, bidx, off);
            if (ob > best || (ob == best && oi < bidx)) { best = ob; bidx = oi; }
        }
        int R = by * 128 + ty * 8 + i;   // R = t*512 + b
        int t = R >> 9;
        int b = R & 511;
        float* orow = out + (size_t)b * (Tt * NCC) + t * NCC;
        #pragma unroll
        for (int j = 0; j < 8; j++) {
            int col = tx * 8 + j;
            orow[col] = (col == bidx) ? 1.f : 0.f;
        }
    }
}

// ---------------- copy final h, c to output ---------------------------------
__global__ void copy_final_kernel(float* __restrict__ out) {
    int i = blockIdx.x * blockDim.x + threadIdx.x;
    if (i < BRNN) {
        out[BT * NCC + i] = g_hall[(size_t)Tt * BRNN + i];       // final h
        out[BT * NCC + BRNN + i] = g_c0[i];                      // final c (t=31 odd -> c0)
    }
}

// ---------------- launch -----------------------------------------------------
extern "C" void kernel_launch(void* const* d_in, const int* in_sizes, int n_in,
                              void* d_out, int out_size) {
    const float* f_pool = (const float*)d_in[0];
    const float* gt     = (const float*)d_in[1];
    const float* W      = (const float*)d_in[2];
    const float* rec    = (const float*)d_in[3];
    const float* bias   = (const float*)d_in[4];
    const float* sw     = (const float*)d_in[5];
    const float* sb     = (const float*)d_in[6];
    float* out = (float*)d_out;

    init_zero_kernel<<<(BRNN + 255) / 256, 256>>>();
    assemble_X_kernel<<<(BT * DIN + 255) / 256, 256>>>(f_pool, gt);

    dim3 gz(16, 128);
    gemm_Z_kernel<<<gz, 256>>>(W, bias);

    const int gate_threads = Bb * (RNN / 4);
    for (int t = 0; t < Tt; t++) {
        if (t > 0) {
            dim3 gg(16, 4, KS);
            lstm_gemm_kernel<<<gg, 256>>>(t, rec);
        }
        gate_kernel<<<(gate_threads + 255) / 256, 256>>>(t, t > 0 ? 1 : 0);
    }

    logits_argmax_kernel<<<128, 256>>>(sw, sb, out);
    copy_final_kernel<<<(BRNN + 255) / 256, 256>>>(out);
}

// round 4
// speedup vs baseline: 1.3940x; 1.0013x over previous
#include <cuda_runtime.h>
#include <math.h>

#define Bb    512
#define Tt    32
#define DEPTH 512
#define RNN   512
#define NCC   128
#define DIN   640          // DEPTH + NCC
#define G4    2048         // 4*RNN
#define BT    16384        // Bb*Tt
#define BRNN  (Bb*RNN)     // 262144
#define KS    4            // split-K slices for recurrent GEMM

// ---------------- scratch (device globals: no allocation allowed) ----------
__device__ float g_X[BT * DIN];            // assembled inputs  [16384 x 640]
__device__ float g_Z[BT * G4];             // precomputed input gates [16384 x 2048]
__device__ float g_hall[(Tt + 1) * BRNN];  // h per step; slot 0 = zeros
__device__ float g_c0[BRNN];
__device__ float g_c1[BRNN];
__device__ float g_part[KS * Bb * G4];     // split-K partials [4][512][2048]

// ---------------- init: zero h0 and c0 -------------------------------------
__global__ void init_zero_kernel() {
    int i = blockIdx.x * blockDim.x + threadIdx.x;
    if (i < BRNN) { g_hall[i] = 0.f; g_c0[i] = 0.f; }
}

// ---------------- assemble X = [f_pool[:,t,:], gt[:,t-1,:]] ----------------
__global__ void assemble_X_kernel(const float* __restrict__ f_pool,
                                  const float* __restrict__ gt) {
    int idx = blockIdx.x * blockDim.x + threadIdx.x;
    if (idx >= BT * DIN) return;
    int r = idx / DIN;          // r = b*32 + t
    int k = idx - r * DIN;
    float v;
    if (k < DEPTH) {
        v = f_pool[r * DEPTH + k];
    } else {
        int t = r & 31;
        v = (t == 0) ? 0.f : gt[(r - 1) * NCC + (k - DEPTH)];
    }
    g_X[idx] = v;
}

// ============================================================================
// Pipelined 128x128 GEMM bodies: double-buffered smem + register prefetch,
// ONE __syncthreads per k-iteration. 256 threads, 8x8 microtile.
// ============================================================================

// ---------------- Z = X @ kernel + bias  (M=16384, N=2048, K=640) ----------
__global__ __launch_bounds__(256) void gemm_Z_kernel(
    const float* __restrict__ W, const float* __restrict__ bias) {
    __shared__ float As[2][8][132];
    __shared__ float Bs[2][8][128];
    const int bx = blockIdx.x;       // 0..15   (N tiles)
    const int by = blockIdx.y;       // 0..127  (M tiles)
    const int tid = threadIdx.x;
    const int tx = tid & 15;
    const int ty = tid >> 4;
    const int la_r = tid >> 1;
    const int la_k = (tid & 1) * 4;
    const int lb_k = tid >> 5;
    const int lb_j = (tid & 31) * 4;
    const float* Aptr = g_X + (size_t)(by * 128 + la_r) * DIN + la_k;
    const float* Bptr = W + (size_t)lb_k * G4 + bx * 128 + lb_j;

    float acc[8][8];
    #pragma unroll
    for (int i = 0; i < 8; i++)
        #pragma unroll
        for (int j = 0; j < 8; j++) acc[i][j] = 0.f;

    float4 aN = *(const float4*)(Aptr);
    float4 bN = *(const float4*)(Bptr);
    int buf = 0;
    for (int k0 = 0; k0 < DIN; k0 += 8) {
        As[buf][la_k + 0][la_r] = aN.x; As[buf][la_k + 1][la_r] = aN.y;
        As[buf][la_k + 2][la_r] = aN.z; As[buf][la_k + 3][la_r] = aN.w;
        *(float4*)&Bs[buf][lb_k][lb_j] = bN;
        if (k0 + 8 < DIN) {
            aN = *(const float4*)(Aptr + k0 + 8);
            bN = *(const float4*)(Bptr + (size_t)(k0 + 8) * G4);
        }
        __syncthreads();
        #pragma unroll
        for (int kk = 0; kk < 8; kk++) {
            float av[8], bv[8];
            #pragma unroll
            for (int i = 0; i < 8; i++) av[i] = As[buf][kk][ty * 8 + i];
            #pragma unroll
            for (int j = 0; j < 8; j++) bv[j] = Bs[buf][kk][tx * 8 + j];
            #pragma unroll
            for (int i = 0; i < 8; i++)
                #pragma unroll
                for (int j = 0; j < 8; j++) acc[i][j] += av[i] * bv[j];
        }
        buf ^= 1;
    }
    #pragma unroll
    for (int i = 0; i < 8; i++) {
        int row = by * 128 + ty * 8 + i;
        int col = bx * 128 + tx * 8;
        #pragma unroll
        for (int j = 0; j < 8; j += 4) {
            float4 v;
            v.x = acc[i][j + 0] + bias[col + j + 0];
            v.y = acc[i][j + 1] + bias[col + j + 1];
            v.z = acc[i][j + 2] + bias[col + j + 2];
            v.w = acc[i][j + 3] + bias[col + j + 3];
            *(float4*)&g_Z[(size_t)row * G4 + col + j] = v;
        }
    }
}

// ---------------- recurrent GEMM: partials = h_prev @ rec (split-K=4) -------
// M=512, N=2048, K=512 split into 4 slices of 128. grid (16,4,4), 256 thr.
__global__ __launch_bounds__(256) void lstm_gemm_kernel(
    int t, const float* __restrict__ rec) {
    __shared__ float As[2][8][132];
    __shared__ float Bs[2][8][128];
    const int n0 = blockIdx.x * 128;
    const int m0 = blockIdx.y * 128;
    const int kb = blockIdx.z * 128;
    const float* __restrict__ A = g_hall + (size_t)t * BRNN;  // [512 x 512]
    const int tid = threadIdx.x;
    const int tx = tid & 15;
    const int ty = tid >> 4;
    const int la_r = tid >> 1;
    const int la_k = (tid & 1) * 4;
    const int lb_k = tid >> 5;
    const int lb_j = (tid & 31) * 4;
    const float* Aptr = A + (size_t)(m0 + la_r) * RNN + kb + la_k;
    const float* Bptr = rec + (size_t)(kb + lb_k) * G4 + n0 + lb_j;

    float acc[8][8];
    #pragma unroll
    for (int i = 0; i < 8; i++)
        #pragma unroll
        for (int j = 0; j < 8; j++) acc[i][j] = 0.f;

    float4 aN = *(const float4*)(Aptr);
    float4 bN = *(const float4*)(Bptr);
    int buf = 0;
    #pragma unroll 4
    for (int k0 = 0; k0 < 128; k0 += 8) {
        As[buf][la_k + 0][la_r] = aN.x; As[buf][la_k + 1][la_r] = aN.y;
        As[buf][la_k + 2][la_r] = aN.z; As[buf][la_k + 3][la_r] = aN.w;
        *(float4*)&Bs[buf][lb_k][lb_j] = bN;
        if (k0 + 8 < 128) {
            aN = *(const float4*)(Aptr + k0 + 8);
            bN = *(const float4*)(Bptr + (size_t)(k0 + 8) * G4);
        }
        __syncthreads();
        #pragma unroll
        for (int kk = 0; kk < 8; kk++) {
            float av[8], bv[8];
            #pragma unroll
            for (int i = 0; i < 8; i++) av[i] = As[buf][kk][ty * 8 + i];
            #pragma unroll
            for (int j = 0; j < 8; j++) bv[j] = Bs[buf][kk][tx * 8 + j];
            #pragma unroll
            for (int i = 0; i < 8; i++)
                #pragma unroll
                for (int j = 0; j < 8; j++) acc[i][j] += av[i] * bv[j];
        }
        buf ^= 1;
    }

    float* __restrict__ P = g_part + (size_t)blockIdx.z * (Bb * G4);
    #pragma unroll
    for (int i = 0; i < 8; i++) {
        int row = m0 + ty * 8 + i;
        int col = n0 + tx * 8;
        #pragma unroll
        for (int j = 0; j < 8; j += 4) {
            float4 v;
            v.x = acc[i][j + 0]; v.y = acc[i][j + 1];
            v.z = acc[i][j + 2]; v.w = acc[i][j + 3];
            *(float4*)&P[(size_t)row * G4 + col + j] = v;
        }
    }
}

// ---------------- gating: combine partials + Z + c -> h,c -------------------
__device__ __forceinline__ float sigm(float x) { return 1.f / (1.f + expf(-x)); }

__global__ __launch_bounds__(256) void gate_kernel(int t, int use_part) {
    int idx = blockIdx.x * blockDim.x + threadIdx.x;
    if (idx >= Bb * (RNN / 4)) return;
    int r4 = (idx & 127) * 4;
    int b  = idx >> 7;
    const float* __restrict__ c_prev = (t & 1) ? g_c1 : g_c0;
    float* __restrict__ c_out = (t & 1) ? g_c0 : g_c1;
    float* __restrict__ h_out = g_hall + (size_t)(t + 1) * BRNN;

    float4 gz[4];
    #pragma unroll
    for (int g = 0; g < 4; g++) {
        size_t zo = ((size_t)b * Tt + t) * G4 + g * RNN + r4;
        float4 s = *(const float4*)(g_Z + zo);
        if (use_part) {
            size_t po = (size_t)b * G4 + g * RNN + r4;
            #pragma unroll
            for (int ks = 0; ks < KS; ks++) {
                float4 p = *(const float4*)(g_part + (size_t)ks * (Bb * G4) + po);
                s.x += p.x; s.y += p.y; s.z += p.z; s.w += p.w;
            }
        }
        gz[g] = s;
    }
    float4 cp = *(const float4*)(c_prev + (size_t)b * RNN + r4);

    float4 cv, hv;
    {
        float c2;
        c2 = sigm(gz[1].x) * cp.x + sigm(gz[0].x) * tanhf(gz[2].x);
        cv.x = c2; hv.x = sigm(gz[3].x) * tanhf(c2);
        c2 = sigm(gz[1].y) * cp.y + sigm(gz[0].y) * tanhf(gz[2].y);
        cv.y = c2; hv.y = sigm(gz[3].y) * tanhf(c2);
        c2 = sigm(gz[1].z) * cp.z + sigm(gz[0].z) * tanhf(gz[2].z);
        cv.z = c2; hv.z = sigm(gz[3].z) * tanhf(c2);
        c2 = sigm(gz[1].w) * cp.w + sigm(gz[0].w) * tanhf(gz[2].w);
        cv.w = c2; hv.w = sigm(gz[3].w) * tanhf(c2);
    }
    *(float4*)(c_out + (size_t)b * RNN + r4) = cv;
    *(float4*)(h_out + (size_t)b * RNN + r4) = hv;
}

// ---------------- batched logits + argmax + one-hot -------------------------
// M=16384, N=128 (full), K=512. Pipelined like the others.
__global__ __launch_bounds__(256) void logits_argmax_kernel(
    const float* __restrict__ sw, const float* __restrict__ sb,
    float* __restrict__ out) {
    __shared__ float As[2][8][132];
    __shared__ float Bs[2][8][128];
    const int by = blockIdx.x;   // 0..127
    const int tid = threadIdx.x;
    const int tx = tid & 15;
    const int ty = tid >> 4;
    const int la_r = tid >> 1;
    const int la_k = (tid & 1) * 4;
    const int lb_k = tid >> 5;
    const int lb_j = (tid & 31) * 4;
    const float* Aptr = g_hall + BRNN + (size_t)(by * 128 + la_r) * RNN + la_k;
    const float* Bptr = sw + (size_t)lb_k * NCC + lb_j;

    float acc[8][8];
    #pragma unroll
    for (int i = 0; i < 8; i++)
        #pragma unroll
        for (int j = 0; j < 8; j++) acc[i][j] = 0.f;

    float4 aN = *(const float4*)(Aptr);
    float4 bN = *(const float4*)(Bptr);
    int buf = 0;
    for (int k0 = 0; k0 < RNN; k0 += 8) {
        As[buf][la_k + 0][la_r] = aN.x; As[buf][la_k + 1][la_r] = aN.y;
        As[buf][la_k + 2][la_r] = aN.z; As[buf][la_k + 3][la_r] = aN.w;
        *(float4*)&Bs[buf][lb_k][lb_j] = bN;
        if (k0 + 8 < RNN) {
            aN = *(const float4*)(Aptr + k0 + 8);
            bN = *(const float4*)(Bptr + (size_t)(k0 + 8) * NCC);
        }
        __syncthreads();
        #pragma unroll
        for (int kk = 0; kk < 8; kk++) {
            float av[8], bv[8];
            #pragma unroll
            for (int i = 0; i < 8; i++) av[i] = As[buf][kk][ty * 8 + i];
            #pragma unroll
            for (int j = 0; j < 8; j++) bv[j] = Bs[buf][kk][tx * 8 + j];
            #pragma unroll
            for (int i = 0; i < 8; i++)
                #pragma unroll
                for (int j = 0; j < 8; j++) acc[i][j] += av[i] * bv[j];
        }
        buf ^= 1;
    }

    #pragma unroll
    for (int i = 0; i < 8; i++) {
        float best = -1e30f;
        int bidx = 0;
        #pragma unroll
        for (int j = 0; j < 8; j++) {
            float v = acc[i][j] + sb[tx * 8 + j];
            if (v > best) { best = v; bidx = tx * 8 + j; }
        }
        #pragma unroll
        for (int off = 8; off >= 1; off >>= 1) {
            float ob = __shfl_xor_sync(0xffffffffu, best, off);
            int oi = __shfl_xor_sync(0xffffffffu, bidx, off);
            if (ob > best || (ob == best && oi < bidx)) { best = ob; bidx = oi; }
        }
        int R = by * 128 + ty * 8 + i;   // R = t*512 + b
        int t = R >> 9;
        int b = R & 511;
        float* orow = out + (size_t)b * (Tt * NCC) + t * NCC;
        #pragma unroll
        for (int j = 0; j < 8; j++) {
            int col = tx * 8 + j;
            orow[col] = (col == bidx) ? 1.f : 0.f;
        }
    }
}

// ---------------- copy final h, c to output ---------------------------------
__global__ void copy_final_kernel(float* __restrict__ out) {
    int i = blockIdx.x * blockDim.x + threadIdx.x;
    if (i < BRNN) {
        out[BT * NCC + i] = g_hall[(size_t)Tt * BRNN + i];       // final h
        out[BT * NCC + BRNN + i] = g_c0[i];                      // final c (t=31 odd -> c0)
    }
}

// ---------------- launch -----------------------------------------------------
extern "C" void kernel_launch(void* const* d_in, const int* in_sizes, int n_in,
                              void* d_out, int out_size) {
    const float* f_pool = (const float*)d_in[0];
    const float* gt     = (const float*)d_in[1];
    const float* W      = (const float*)d_in[2];
    const float* rec    = (const float*)d_in[3];
    const float* bias   = (const float*)d_in[4];
    const float* sw     = (const float*)d_in[5];
    const float* sb     = (const float*)d_in[6];
    float* out = (float*)d_out;

    init_zero_kernel<<<(BRNN + 255) / 256, 256>>>();
    assemble_X_kernel<<<(BT * DIN + 255) / 256, 256>>>(f_pool, gt);

    dim3 gz(16, 128);
    gemm_Z_kernel<<<gz, 256>>>(W, bias);

    const int gate_threads = Bb * (RNN / 4);
    for (int t = 0; t < Tt; t++) {
        if (t > 0) {
            dim3 gg(16, 4, KS);
            lstm_gemm_kernel<<<gg, 256>>>(t, rec);
        }
        gate_kernel<<<(gate_threads + 255) / 256, 256>>>(t, t > 0 ? 1 : 0);
    }

    logits_argmax_kernel<<<128, 256>>>(sw, sb, out);
    copy_final_kernel<<<(BRNN + 255) / 256, 256>>>(out);
}

// round 6
// speedup vs baseline: 2.1800x; 1.5638x over previous
#include <cuda_runtime.h>
#include <cuda_bf16.h>
#include <math.h>
#include <stdint.h>

#define Bb    512
#define Tt    32
#define DEPTH 512
#define RNN   512
#define NCC   128
#define G4    2048
#define BT    16384
#define BRNN  (Bb*RNN)
#define SMEM_DYN 197632   // 1K align slack + 2 x 96KB chunk buffers

// ---------------- device scratch -------------------------------------------
__device__ float g_Z[BT * G4];
__device__ float g_hall[(Tt + 1) * BRNN];
__device__ float g_c0[BRNN];
__device__ float g_c1[BRNN];
__device__ float g_part[2 * Bb * G4];   // split-K=2 partials for h@rec
// bf16 3-way splits as pre-swizzled SW128 [128x64] tile images (16KB each)
__device__ __align__(16) unsigned short g_Xs[3 * 128 * 10 * 8192];
__device__ __align__(16) unsigned short g_Ws[3 * 16 * 10 * 8192];
__device__ __align__(16) unsigned short g_Rs[3 * 16 * 8 * 8192];
__device__ __align__(16) unsigned short g_hs[3 * 4 * 8 * 8192];

// ---------------- PTX helpers ----------------------------------------------
static __device__ __forceinline__ uint32_t s2u(const void* p) {
    uint32_t a;
    asm("{ .reg .u64 t; cvta.to.shared.u64 t, %1; cvt.u32.u64 %0, t; }" : "=r"(a) : "l"(p));
    return a;
}
static __device__ __forceinline__ void cp16(uint32_t d, const void* s) {
    asm volatile("cp.async.cg.shared.global [%0], [%1], 16;" :: "r"(d), "l"(s));
}
#define CP_COMMIT() asm volatile("cp.async.commit_group;" ::: "memory")
#define CP_WAIT(n)  asm volatile("cp.async.wait_group %0;" :: "n"(n) : "memory")

static __device__ __forceinline__ void ldsm4(uint32_t* r, uint32_t a) {
    asm volatile("ldmatrix.sync.aligned.m8n8.x4.shared.b16 {%0,%1,%2,%3}, [%4];"
        : "=r"(r[0]), "=r"(r[1]), "=r"(r[2]), "=r"(r[3]) : "r"(a));
}
static __device__ __forceinline__ void ldsm2(uint32_t* r, uint32_t a) {
    asm volatile("ldmatrix.sync.aligned.m8n8.x2.shared.b16 {%0,%1}, [%2];"
        : "=r"(r[0]), "=r"(r[1]) : "r"(a));
}
static __device__ __forceinline__ void mma16816(float* d, const uint32_t* a, const uint32_t* b) {
    asm volatile("mma.sync.aligned.m16n8k16.row.col.f32.bf16.bf16.f32 "
        "{%0,%1,%2,%3}, {%4,%5,%6,%7}, {%8,%9}, {%0,%1,%2,%3};"
        : "+f"(d[0]), "+f"(d[1]), "+f"(d[2]), "+f"(d[3])
        : "r"(a[0]), "r"(a[1]), "r"(a[2]), "r"(a[3]), "r"(b[0]), "r"(b[1]));
}

// ---------------- split helpers --------------------------------------------
static __device__ __forceinline__ void split3(float x, unsigned short& s1,
                                              unsigned short& s2, unsigned short& s3) {
    __nv_bfloat16 b1 = __float2bfloat16_rn(x);
    float r1 = x - __bfloat162float(b1);
    __nv_bfloat16 b2 = __float2bfloat16_rn(r1);
    float r2 = r1 - __bfloat162float(b2);
    __nv_bfloat16 b3 = __float2bfloat16_rn(r2);
    s1 = __bfloat16_as_ushort(b1); s2 = __bfloat16_as_ushort(b2); s3 = __bfloat16_as_ushort(b3);
}
static __device__ __forceinline__ uint32_t swz(uint32_t o) { return o ^ ((o >> 3) & 0x70); }
// write one float4's 3 splits into [128 x 64bf16] SW128 tile images
static __device__ __forceinline__ void put_split4(char* base, int s_mul, int mt, int nch,
                                                  int c, int rb, int kk, float4 v) {
    uint32_t sw = swz(((uint32_t)(rb >> 3) << 10) + ((uint32_t)(rb & 7) << 7) + ((uint32_t)kk << 1));
    float xs[4] = {v.x, v.y, v.z, v.w};
    unsigned short a[3][4];
    #pragma unroll
    for (int i = 0; i < 4; i++) split3(xs[i], a[0][i], a[1][i], a[2][i]);
    #pragma unroll
    for (int s = 0; s < 3; s++) {
        ushort4 o = make_ushort4(a[s][0], a[s][1], a[s][2], a[s][3]);
        *(ushort4*)(base + ((size_t)(s * s_mul + mt) * nch + c) * 16384 + sw) = o;
    }
}

// ---------------- init / prep ----------------------------------------------
__global__ void init_zero_kernel() {
    int i = blockIdx.x * blockDim.x + threadIdx.x;
    if (i < BRNN) { g_hall[i] = 0.f; g_c0[i] = 0.f; }
}

__global__ void assemble_splitX_kernel(const float* __restrict__ f_pool,
                                       const float* __restrict__ gt) {
    int idx = blockIdx.x * blockDim.x + threadIdx.x;
    if (idx >= BT * 160) return;
    int r = idx / 160, k0 = (idx - r * 160) * 4;
    float4 v;
    if (k0 < DEPTH) v = *(const float4*)(f_pool + (size_t)r * DEPTH + k0);
    else {
        int t = r & 31;
        v = (t == 0) ? make_float4(0.f, 0.f, 0.f, 0.f)
                     : *(const float4*)(gt + (size_t)(r - 1) * NCC + (k0 - DEPTH));
    }
    put_split4((char*)g_Xs, 128, r >> 7, 10, k0 >> 6, r & 127, k0 & 63, v);
}

__global__ void split_W_kernel(const float* __restrict__ W) {
    int idx = blockIdx.x * blockDim.x + threadIdx.x;
    if (idx >= 160 * 2048) return;
    int kc = idx >> 11, n = idx & 2047, k0 = kc * 4;
    float4 v;
    v.x = W[(size_t)(k0 + 0) * G4 + n]; v.y = W[(size_t)(k0 + 1) * G4 + n];
    v.z = W[(size_t)(k0 + 2) * G4 + n]; v.w = W[(size_t)(k0 + 3) * G4 + n];
    put_split4((char*)g_Ws, 16, n >> 7, 10, k0 >> 6, n & 127, k0 & 63, v);
}

__global__ void split_rec_kernel(const float* __restrict__ rec) {
    int idx = blockIdx.x * blockDim.x + threadIdx.x;
    if (idx >= 128 * 2048) return;
    int kc = idx >> 11, n = idx & 2047, k0 = kc * 4;
    float4 v;
    v.x = rec[(size_t)(k0 + 0) * G4 + n]; v.y = rec[(size_t)(k0 + 1) * G4 + n];
    v.z = rec[(size_t)(k0 + 2) * G4 + n]; v.w = rec[(size_t)(k0 + 3) * G4 + n];
    put_split4((char*)g_Rs, 16, n >> 7, 8, k0 >> 6, n & 127, k0 & 63, v);
}

// ============ 6-product split GEMM via mma.sync bf16 HMMA ===================
// CTA tile 128x128, 8 warps (warp tile 64x32), cp.async double-buffered.
// mode 0: g_Z = X@W + bias   grid(16,128,1), chunks 0..9
// mode 1: g_part[z] = h@rec  grid(16,4,2),   chunks z*4..z*4+3
__global__ __launch_bounds__(256) void hmma6_kernel(int mode, const float* __restrict__ bias_in) {
    extern __shared__ char dsm[];
    const char* A8; const char* B8; int nmt, nch; const float* bias; float* out;
    int c0 = 0, c1;
    if (mode == 0) {
        A8 = (const char*)g_Xs; B8 = (const char*)g_Ws;
        nmt = 128; nch = 10; bias = bias_in; out = g_Z; c1 = 10;
    } else {
        A8 = (const char*)g_hs; B8 = (const char*)g_Rs;
        nmt = 4; nch = 8; bias = nullptr;
        out = g_part + (size_t)blockIdx.z * (Bb * G4);
        c0 = blockIdx.z * 4; c1 = c0 + 4;
    }
    const int tid = threadIdx.x, lane = tid & 31, wid = tid >> 5;
    const int mt = blockIdx.y, nt = blockIdx.x;
    const int wm = wid & 1, wn = wid >> 1;      // warp tile: rows wm*64, cols wn*32
    uint32_t buf0 = (s2u(dsm) + 1023u) & ~1023u;

    // ldmatrix address precompute (SW128 swizzle folds to constant XOR)
    const int l7 = lane & 7;
    const uint32_t xm = (uint32_t)l7 << 4;
    const int asub = lane >> 3;
    const uint32_t akoff = (uint32_t)(asub >> 1) * 16;
    const uint32_t bkoff = (uint32_t)((lane >> 3) & 1) * 16;
    uint32_t arb[4], brb[4];
    #pragma unroll
    for (int m4 = 0; m4 < 4; m4++) {
        int row = wm * 64 + m4 * 16 + (asub & 1) * 8 + l7;
        arb[m4] = (uint32_t)(row >> 3) * 1024u + (uint32_t)l7 * 128u;
    }
    #pragma unroll
    for (int n4 = 0; n4 < 4; n4++) {
        int row = wn * 32 + n4 * 8 + l7;
        brb[n4] = (uint32_t)(row >> 3) * 1024u + (uint32_t)l7 * 128u + 49152u;
    }

    float acc[4][4][4];
    #pragma unroll
    for (int m4 = 0; m4 < 4; m4++)
        #pragma unroll
        for (int n4 = 0; n4 < 4; n4++)
            #pragma unroll
            for (int e = 0; e < 4; e++) acc[m4][n4][e] = 0.f;

    auto load_chunk = [&](int c, int bb) {
        uint32_t sb = buf0 + (uint32_t)bb * 98304u;
        #pragma unroll
        for (int tau = 0; tau < 6; tau++) {
            const char* g = (tau < 3)
                ? A8 + ((size_t)(tau * nmt + mt) * nch + c) * 16384
                : B8 + ((size_t)((tau - 3) * 16 + nt) * nch + c) * 16384;
            uint32_t sdst = sb + (uint32_t)tau * 16384u + (uint32_t)tid * 16u;
            const char* gs = g + tid * 16;
            #pragma unroll
            for (int u = 0; u < 4; u++) cp16(sdst + u * 4096u, gs + u * 4096);
        }
    };

    load_chunk(c0, 0);
    CP_COMMIT();
    for (int c = c0; c < c1; c++) {
        int cur = (c - c0) & 1;
        if (c + 1 < c1) { load_chunk(c + 1, cur ^ 1); CP_COMMIT(); CP_WAIT(1); }
        else CP_WAIT(0);
        __syncthreads();
        uint32_t sb = buf0 + (uint32_t)cur * 98304u;
        #pragma unroll
        for (int ks = 0; ks < 4; ks++) {
            uint32_t kb = (uint32_t)ks * 32;
            uint32_t a[3][4][4];
            #pragma unroll
            for (int s = 0; s < 3; s++) {
                uint32_t ab = sb + (uint32_t)s * 16384u + ((kb + akoff) ^ xm);
                #pragma unroll
                for (int m4 = 0; m4 < 4; m4++) ldsm4(a[s][m4], ab + arb[m4]);
            }
            #pragma unroll
            for (int j = 0; j < 3; j++) {
                uint32_t b[4][2];
                uint32_t bbq = sb + (uint32_t)j * 16384u + ((kb + bkoff) ^ xm);
                #pragma unroll
                for (int n4 = 0; n4 < 4; n4++) ldsm2(b[n4], bbq + brb[n4]);
                #pragma unroll
                for (int i = 0; i + j < 3; i++)        // 6 pairs total (i+j<=2)
                    #pragma unroll
                    for (int m4 = 0; m4 < 4; m4++)
                        #pragma unroll
                        for (int n4 = 0; n4 < 4; n4++)
                            mma16816(acc[m4][n4], a[i][m4], b[n4]);
            }
        }
        __syncthreads();
    }

    // epilogue: m16n8 fragment -> gmem, optional bias
    #pragma unroll
    for (int m4 = 0; m4 < 4; m4++) {
        int grow = mt * 128 + wm * 64 + m4 * 16 + (lane >> 2);
        #pragma unroll
        for (int n4 = 0; n4 < 4; n4++) {
            int gcol = nt * 128 + wn * 32 + n4 * 8 + (lane & 3) * 2;
            float b0 = 0.f, b1 = 0.f;
            if (bias) { b0 = bias[gcol]; b1 = bias[gcol + 1]; }
            float2 v;
            v.x = acc[m4][n4][0] + b0; v.y = acc[m4][n4][1] + b1;
            *(float2*)(out + (size_t)grow * G4 + gcol) = v;
            v.x = acc[m4][n4][2] + b0; v.y = acc[m4][n4][3] + b1;
            *(float2*)(out + (size_t)(grow + 8) * G4 + gcol) = v;
        }
    }
}

// ---------------- gating + next-step h splits -------------------------------
__device__ __forceinline__ float sigm(float x) { return 1.f / (1.f + expf(-x)); }

__global__ __launch_bounds__(256) void gate_kernel(int t, int use_part) {
    int idx = blockIdx.x * blockDim.x + threadIdx.x;
    if (idx >= Bb * (RNN / 4)) return;
    int r4 = (idx & 127) * 4, b = idx >> 7;
    const float* __restrict__ c_prev = (t & 1) ? g_c1 : g_c0;
    float* __restrict__ c_out = (t & 1) ? g_c0 : g_c1;
    float* __restrict__ h_out = g_hall + (size_t)(t + 1) * BRNN;

    float4 gz[4];
    #pragma unroll
    for (int g = 0; g < 4; g++) {
        size_t zo = ((size_t)b * Tt + t) * G4 + g * RNN + r4;
        float4 s = *(const float4*)(g_Z + zo);
        if (use_part) {
            size_t po = (size_t)b * G4 + g * RNN + r4;
            float4 p = *(const float4*)(g_part + po);
            float4 q = *(const float4*)(g_part + (size_t)(Bb * G4) + po);
            s.x += p.x + q.x; s.y += p.y + q.y; s.z += p.z + q.z; s.w += p.w + q.w;
        }
        gz[g] = s;
    }
    float4 cp = *(const float4*)(c_prev + (size_t)b * RNN + r4);
    float4 cv, hv;
    {
        float c2;
        c2 = sigm(gz[1].x) * cp.x + sigm(gz[0].x) * tanhf(gz[2].x); cv.x = c2; hv.x = sigm(gz[3].x) * tanhf(c2);
        c2 = sigm(gz[1].y) * cp.y + sigm(gz[0].y) * tanhf(gz[2].y); cv.y = c2; hv.y = sigm(gz[3].y) * tanhf(c2);
        c2 = sigm(gz[1].z) * cp.z + sigm(gz[0].z) * tanhf(gz[2].z); cv.z = c2; hv.z = sigm(gz[3].z) * tanhf(c2);
        c2 = sigm(gz[1].w) * cp.w + sigm(gz[0].w) * tanhf(gz[2].w); cv.w = c2; hv.w = sigm(gz[3].w) * tanhf(c2);
    }
    *(float4*)(c_out + (size_t)b * RNN + r4) = cv;
    *(float4*)(h_out + (size_t)b * RNN + r4) = hv;
    put_split4((char*)g_hs, 4, b >> 7, 8, r4 >> 6, b & 127, r4 & 63, hv);
}

// ---------------- logits + argmax + one-hot (exact fp32 SIMT) ---------------
__global__ __launch_bounds__(256) void logits_argmax_kernel(
    const float* __restrict__ sw, const float* __restrict__ sb, float* __restrict__ out) {
    __shared__ float As[2][8][132];
    __shared__ float Bs[2][8][128];
    const int by = blockIdx.x, tid = threadIdx.x;
    const int tx = tid & 15, ty = tid >> 4;
    const int la_r = tid >> 1, la_k = (tid & 1) * 4;
    const int lb_k = tid >> 5, lb_j = (tid & 31) * 4;
    const float* Aptr = g_hall + BRNN + (size_t)(by * 128 + la_r) * RNN + la_k;
    const float* Bptr = sw + (size_t)lb_k * NCC + lb_j;

    float acc[8][8];
    #pragma unroll
    for (int i = 0; i < 8; i++)
        #pragma unroll
        for (int j = 0; j < 8; j++) acc[i][j] = 0.f;

    float4 aN = *(const float4*)(Aptr);
    float4 bN = *(const float4*)(Bptr);
    int buf = 0;
    for (int k0 = 0; k0 < RNN; k0 += 8) {
        As[buf][la_k + 0][la_r] = aN.x; As[buf][la_k + 1][la_r] = aN.y;
        As[buf][la_k + 2][la_r] = aN.z; As[buf][la_k + 3][la_r] = aN.w;
        *(float4*)&Bs[buf][lb_k][lb_j] = bN;
        if (k0 + 8 < RNN) {
            aN = *(const float4*)(Aptr + k0 + 8);
            bN = *(const float4*)(Bptr + (size_t)(k0 + 8) * NCC);
        }
        __syncthreads();
        #pragma unroll
        for (int kk = 0; kk < 8; kk++) {
            float av[8], bv[8];
            #pragma unroll
            for (int i = 0; i < 8; i++) av[i] = As[buf][kk][ty * 8 + i];
            #pragma unroll
            for (int j = 0; j < 8; j++) bv[j] = Bs[buf][kk][tx * 8 + j];
            #pragma unroll
            for (int i = 0; i < 8; i++)
                #pragma unroll
                for (int j = 0; j < 8; j++) acc[i][j] += av[i] * bv[j];
        }
        buf ^= 1;
    }
    #pragma unroll
    for (int i = 0; i < 8; i++) {
        float best = -1e30f; int bidx = 0;
        #pragma unroll
        for (int j = 0; j < 8; j++) {
            float v = acc[i][j] + sb[tx * 8 + j];
            if (v > best) { best = v; bidx = tx * 8 + j; }
        }
        #pragma unroll
        for (int off = 8; off >= 1; off >>= 1) {
            float ob = __shfl_xor_sync(0xffffffffu, best, off);
            int oi = __shfl_xor_sync(0xffffffffu, bidx, off);
            if (ob > best || (ob == best && oi < bidx)) { best = ob; bidx = oi; }
        }
        int R = by * 128 + ty * 8 + i;
        int t = R >> 9, b = R & 511;
        float* orow = out + (size_t)b * (Tt * NCC) + t * NCC;
        #pragma unroll
        for (int j = 0; j < 8; j++) { int col = tx * 8 + j; orow[col] = (col == bidx) ? 1.f : 0.f; }
    }
}

__global__ void copy_final_kernel(float* __restrict__ out) {
    int i = blockIdx.x * blockDim.x + threadIdx.x;
    if (i < BRNN) {
        out[BT * NCC + i] = g_hall[(size_t)Tt * BRNN + i];
        out[BT * NCC + BRNN + i] = g_c0[i];   // t=31 odd -> wrote g_c0
    }
}

// ---------------- launch -----------------------------------------------------
extern "C" void kernel_launch(void* const* d_in, const int* in_sizes, int n_in,
                              void* d_out, int out_size) {
    const float* f_pool = (const float*)d_in[0];
    const float* gt     = (const float*)d_in[1];
    const float* W      = (const float*)d_in[2];
    const float* rec    = (const float*)d_in[3];
    const float* bias   = (const float*)d_in[4];
    const float* sw     = (const float*)d_in[5];
    const float* sb     = (const float*)d_in[6];
    float* out = (float*)d_out;

    cudaFuncSetAttribute(hmma6_kernel, cudaFuncAttributeMaxDynamicSharedMemorySize, SMEM_DYN);

    init_zero_kernel<<<(BRNN + 255) / 256, 256>>>();
    assemble_splitX_kernel<<<(BT * 160 + 255) / 256, 256>>>(f_pool, gt);
    split_W_kernel<<<(160 * 2048 + 255) / 256, 256>>>(W);
    split_rec_kernel<<<(128 * 2048 + 255) / 256, 256>>>(rec);

    hmma6_kernel<<<dim3(16, 128, 1), 256, SMEM_DYN>>>(0, bias);

    const int gate_blocks = (Bb * (RNN / 4) + 255) / 256;
    for (int t = 0; t < Tt; t++) {
        if (t > 0)
            hmma6_kernel<<<dim3(16, 4, 2), 256, SMEM_DYN>>>(1, nullptr);
        gate_kernel<<<gate_blocks, 256>>>(t, t > 0 ? 1 : 0);
    }

    logits_argmax_kernel<<<128, 256>>>(sw, sb, out);
    copy_final_kernel<<<(BRNN + 255) / 256, 256>>>(out);
}